// round 1
// baseline (speedup 1.0000x reference)
#include <cuda_runtime.h>
#include <math.h>

#define HH 512
#define WW 512
#define KK 8
#define HWPIX (HH*WW)

// ---------------- scratch buffers (device globals; no allocation) ----------------
__device__ float g_fm [134217728];  // [K][H][W][64]  fz(0..31) | fc(32..63)
__device__ float g_t64[134217728];  // [K][H][W][64]  relu(mpn1)
__device__ float g_c32[ 67108864];  // [K][H][W][32]  relu(sup1)
__device__ float g_fuse[ 2097152];  // [H][W][K]
__device__ float g_u32 [ 8388608];  // [H][W][32]

// ======================= MLP kernel =======================
// 64 points per block, 128 threads, weights + double-buffered h in smem.
#define HSTRIDE 133
#define OFF_W1 0
#define OFF_B1 384
#define OFF_W2 512
#define OFF_B2 16896
#define OFF_W3 17024
#define OFF_B3 33792
#define OFF_W4 33920
#define OFF_B4 38016
#define OFF_HA 38048
#define OFF_HB (OFF_HA + 64*HSTRIDE)
#define OFF_XS (OFF_HB + 64*HSTRIDE)
#define MLP_SMEM_FLOATS (OFF_XS + 64*8)
#define MLP_SMEM_BYTES  (MLP_SMEM_FLOATS*4)

template<int IN, bool RELU>
__device__ __forceinline__ void mlp_step(const float* __restrict__ hin,
                                         float* __restrict__ hout,
                                         const float* __restrict__ Wf,
                                         const float* __restrict__ bf,
                                         int tu, int tp)
{
    float acc[8][8];
#pragma unroll
    for (int p = 0; p < 8; p++)
#pragma unroll
        for (int u = 0; u < 8; u++) acc[p][u] = 0.f;

#pragma unroll 2
    for (int i = 0; i < IN; i++) {
        float hv[8];
#pragma unroll
        for (int p = 0; p < 8; p++) hv[p] = hin[(tp*8 + p)*HSTRIDE + i];
        float4 w0 = *(const float4*)(Wf + i*128 + tu*8);
        float4 w1 = *(const float4*)(Wf + i*128 + tu*8 + 4);
#pragma unroll
        for (int p = 0; p < 8; p++) {
            acc[p][0] = fmaf(hv[p], w0.x, acc[p][0]);
            acc[p][1] = fmaf(hv[p], w0.y, acc[p][1]);
            acc[p][2] = fmaf(hv[p], w0.z, acc[p][2]);
            acc[p][3] = fmaf(hv[p], w0.w, acc[p][3]);
            acc[p][4] = fmaf(hv[p], w1.x, acc[p][4]);
            acc[p][5] = fmaf(hv[p], w1.y, acc[p][5]);
            acc[p][6] = fmaf(hv[p], w1.z, acc[p][6]);
            acc[p][7] = fmaf(hv[p], w1.w, acc[p][7]);
        }
    }
    float4 b0 = *(const float4*)(bf + tu*8);
    float4 b1 = *(const float4*)(bf + tu*8 + 4);
    float bb[8] = {b0.x, b0.y, b0.z, b0.w, b1.x, b1.y, b1.z, b1.w};
#pragma unroll
    for (int p = 0; p < 8; p++) {
#pragma unroll
        for (int u = 0; u < 8; u++) {
            float v = acc[p][u] + bb[u];
            if (RELU) v = fmaxf(v, 0.f);
            hout[(tp*8 + p)*HSTRIDE + tu*8 + u] = v;
        }
    }
}

__global__ void __launch_bounds__(128, 1) mlp_kernel(
    const float* __restrict__ ray, const float* __restrict__ zbufs,
    const float* __restrict__ W1, const float* __restrict__ b1,
    const float* __restrict__ W2, const float* __restrict__ b2,
    const float* __restrict__ W3, const float* __restrict__ b3,
    const float* __restrict__ W4, const float* __restrict__ b4)
{
    extern __shared__ float sm[];
    const int tid = threadIdx.x;

    // stage all weights in smem (float4 copies; all offsets 16B aligned)
    for (int i = tid; i < 96;   i += 128) ((float4*)(sm+OFF_W1))[i] = ((const float4*)W1)[i];
    for (int i = tid; i < 32;   i += 128) ((float4*)(sm+OFF_B1))[i] = ((const float4*)b1)[i];
    for (int i = tid; i < 4096; i += 128) ((float4*)(sm+OFF_W2))[i] = ((const float4*)W2)[i];
    for (int i = tid; i < 32;   i += 128) ((float4*)(sm+OFF_B2))[i] = ((const float4*)b2)[i];
    for (int i = tid; i < 4192; i += 128) ((float4*)(sm+OFF_W3))[i] = ((const float4*)W3)[i];
    for (int i = tid; i < 32;   i += 128) ((float4*)(sm+OFF_B3))[i] = ((const float4*)b3)[i];
    for (int i = tid; i < 1024; i += 128) ((float4*)(sm+OFF_W4))[i] = ((const float4*)W4)[i];
    for (int i = tid; i < 8;    i += 128) ((float4*)(sm+OFF_B4))[i] = ((const float4*)b4)[i];

    // phase A: build inputs for 64 points
    if (tid < 64) {
        int p  = blockIdx.x*64 + tid;
        int yx = p & (HWPIX - 1);
        int k  = p >> 18;
        const float* r = ray + (size_t)yx*7;
        float ox=r[0], oy=r[1], oz=r[2], dx=r[3], dy=r[4], dz=r[5], cs=r[6];
        float z = zbufs[(size_t)yx*8 + k];
        float s = z / cs;
        float* xs = sm + OFF_XS + tid*8;
        xs[0] = ox + dx*s; xs[1] = oy + dy*s; xs[2] = oz + dz*s;
        xs[3] = dx; xs[4] = dy; xs[5] = dz;
        xs[6] = (z > 0.f) ? 1.f : 0.f;
        // dirs appended as columns 128..130 of layer-3 input buffer
        sm[OFF_HB + tid*HSTRIDE + 128] = dx;
        sm[OFF_HB + tid*HSTRIDE + 129] = dy;
        sm[OFF_HB + tid*HSTRIDE + 130] = dz;
    }
    __syncthreads();

    // layer 1: 3 -> 128 (thread = unit)
    {
        float w0 = sm[OFF_W1 + 0*128 + tid];
        float w1 = sm[OFF_W1 + 1*128 + tid];
        float w2 = sm[OFF_W1 + 2*128 + tid];
        float bb = sm[OFF_B1 + tid];
        for (int t = 0; t < 64; t++) {
            const float* xs = sm + OFF_XS + t*8;
            float v = bb + xs[0]*w0 + xs[1]*w1 + xs[2]*w2;
            sm[OFF_HA + t*HSTRIDE + tid] = fmaxf(v, 0.f);
        }
    }
    __syncthreads();

    const int tu = tid & 15, tp = tid >> 4;
    // layer 2: 128 -> 128 relu  (hA -> hB)
    mlp_step<128, true>(sm+OFF_HA, sm+OFF_HB, sm+OFF_W2, sm+OFF_B2, tu, tp);
    __syncthreads();
    // layer 3: 131 -> 128 relu  (hB(+dirs) -> hA)
    mlp_step<131, true>(sm+OFF_HB, sm+OFF_HA, sm+OFF_W3, sm+OFF_B3, tu, tp);
    __syncthreads();

    // layer 4: 128 -> 32, masked, write to g_fm channels 0..31
    {
        const int tu4 = tid & 3, tp4 = tid >> 2;   // 4 unit-groups x 32 point-groups(2pts)
        float acc[2][8];
#pragma unroll
        for (int pp = 0; pp < 2; pp++)
#pragma unroll
            for (int u = 0; u < 8; u++) acc[pp][u] = 0.f;

#pragma unroll 2
        for (int i = 0; i < 128; i++) {
            float h0 = sm[OFF_HA + (tp4*2 + 0)*HSTRIDE + i];
            float h1 = sm[OFF_HA + (tp4*2 + 1)*HSTRIDE + i];
            float4 w0 = *(const float4*)(sm + OFF_W4 + i*32 + tu4*8);
            float4 w1 = *(const float4*)(sm + OFF_W4 + i*32 + tu4*8 + 4);
            acc[0][0]=fmaf(h0,w0.x,acc[0][0]); acc[0][1]=fmaf(h0,w0.y,acc[0][1]);
            acc[0][2]=fmaf(h0,w0.z,acc[0][2]); acc[0][3]=fmaf(h0,w0.w,acc[0][3]);
            acc[0][4]=fmaf(h0,w1.x,acc[0][4]); acc[0][5]=fmaf(h0,w1.y,acc[0][5]);
            acc[0][6]=fmaf(h0,w1.z,acc[0][6]); acc[0][7]=fmaf(h0,w1.w,acc[0][7]);
            acc[1][0]=fmaf(h1,w0.x,acc[1][0]); acc[1][1]=fmaf(h1,w0.y,acc[1][1]);
            acc[1][2]=fmaf(h1,w0.z,acc[1][2]); acc[1][3]=fmaf(h1,w0.w,acc[1][3]);
            acc[1][4]=fmaf(h1,w1.x,acc[1][4]); acc[1][5]=fmaf(h1,w1.y,acc[1][5]);
            acc[1][6]=fmaf(h1,w1.z,acc[1][6]); acc[1][7]=fmaf(h1,w1.w,acc[1][7]);
        }
        float4 b0 = *(const float4*)(sm + OFF_B4 + tu4*8);
        float4 b1 = *(const float4*)(sm + OFF_B4 + tu4*8 + 4);
        float bb[8] = {b0.x,b0.y,b0.z,b0.w,b1.x,b1.y,b1.z,b1.w};
#pragma unroll
        for (int pp = 0; pp < 2; pp++) {
            int t  = tp4*2 + pp;
            float mk = sm[OFF_XS + t*8 + 6];
            int p  = blockIdx.x*64 + t;
            float4 o0, o1;
            o0.x=(acc[pp][0]+bb[0])*mk; o0.y=(acc[pp][1]+bb[1])*mk;
            o0.z=(acc[pp][2]+bb[2])*mk; o0.w=(acc[pp][3]+bb[3])*mk;
            o1.x=(acc[pp][4]+bb[4])*mk; o1.y=(acc[pp][5]+bb[5])*mk;
            o1.z=(acc[pp][6]+bb[6])*mk; o1.w=(acc[pp][7]+bb[7])*mk;
            *(float4*)&g_fm[(size_t)p*64 + tu4*8]     = o0;
            *(float4*)&g_fm[(size_t)p*64 + tu4*8 + 4] = o1;
        }
    }
}

// ======================= sup1: 3 -> 32, relu =======================
__global__ void sup1_kernel(const float* __restrict__ colors,
                            const float* __restrict__ kw,
                            const float* __restrict__ bw)
{
    __shared__ float wgt[864]; // 3*3*3*32
    int tx = threadIdx.x, ty = threadIdx.y;
    int tid = ty*32 + tx;
    for (int i = tid; i < 864; i += 256) wgt[i] = kw[i];
    __syncthreads();

    int x = blockIdx.x*32 + tx, y = blockIdx.y*8 + ty, k = blockIdx.z;
    float4 acc[8];
#pragma unroll
    for (int j = 0; j < 8; j++) acc[j] = ((const float4*)bw)[j];

    for (int dy = 0; dy < 3; dy++)
    for (int dx = 0; dx < 3; dx++) {
        int iy = y + dy - 1, ix = x + dx - 1;
        if (iy < 0 || iy >= HH || ix < 0 || ix >= WW) continue;
        const float* cp = colors + ((size_t)iy*WW + ix)*24 + k*3;
        float cv[3] = {cp[0], cp[1], cp[2]};
        const float* wr = wgt + (dy*3 + dx)*96;
#pragma unroll
        for (int ic = 0; ic < 3; ic++) {
            float v = cv[ic];
            const float4* w4 = (const float4*)(wr + ic*32);
#pragma unroll
            for (int j = 0; j < 8; j++) {
                float4 w = w4[j];
                acc[j].x = fmaf(v, w.x, acc[j].x);
                acc[j].y = fmaf(v, w.y, acc[j].y);
                acc[j].z = fmaf(v, w.z, acc[j].z);
                acc[j].w = fmaf(v, w.w, acc[j].w);
            }
        }
    }
    float* dst = g_c32 + ((size_t)k*HWPIX + (size_t)y*WW + x)*32;
#pragma unroll
    for (int j = 0; j < 8; j++) {
        float4 o;
        o.x = fmaxf(acc[j].x, 0.f); o.y = fmaxf(acc[j].y, 0.f);
        o.z = fmaxf(acc[j].z, 0.f); o.w = fmaxf(acc[j].w, 0.f);
        ((float4*)dst)[j] = o;
    }
}

// ======================= sup2: 32 -> 32, no relu, write fm[32..63] ===============
// block 128 = 16x8 pixels, tile [32][10][18] (channel-major), weights 9*32*32 smem
__global__ void __launch_bounds__(128, 1) sup2_kernel(const float* __restrict__ kw,
                                                      const float* __restrict__ bw)
{
    extern __shared__ float sm[];
    float* tile = sm;            // 32*180 = 5760
    float* wgt  = sm + 5760;     // 9216
    int tid = threadIdx.x;
    for (int i = tid; i < 2304; i += 128) ((float4*)wgt)[i] = ((const float4*)kw)[i];

    int bx = blockIdx.x, by = blockIdx.y, k = blockIdx.z;
    const float* src = g_c32 + (size_t)k*HWPIX*32;
    for (int idx = tid; idx < 1440; idx += 128) {
        int c4 = idx & 7, pl = idx >> 3;
        int rr = pl/18, cc = pl - rr*18;
        int gy = by*8 + rr - 1, gx = bx*16 + cc - 1;
        float4 v = make_float4(0.f,0.f,0.f,0.f);
        if (gy >= 0 && gy < HH && gx >= 0 && gx < WW)
            v = *(const float4*)&src[((size_t)gy*WW + gx)*32 + c4*4];
        tile[(c4*4+0)*180 + pl] = v.x;
        tile[(c4*4+1)*180 + pl] = v.y;
        tile[(c4*4+2)*180 + pl] = v.z;
        tile[(c4*4+3)*180 + pl] = v.w;
    }
    __syncthreads();

    int lx = tid & 15, ly = tid >> 4;
    float4 acc[8];
#pragma unroll
    for (int j = 0; j < 8; j++) acc[j] = ((const float4*)bw)[j];

    for (int dy = 0; dy < 3; dy++)
    for (int dx = 0; dx < 3; dx++) {
        const float* wr = wgt + (size_t)(dy*3 + dx)*32*32;
        int tb = (ly + dy)*18 + (lx + dx);
        for (int ic = 0; ic < 32; ic++) {
            float v = tile[ic*180 + tb];
            const float4* w4 = (const float4*)(wr + ic*32);
#pragma unroll
            for (int j = 0; j < 8; j++) {
                float4 w = w4[j];
                acc[j].x = fmaf(v, w.x, acc[j].x);
                acc[j].y = fmaf(v, w.y, acc[j].y);
                acc[j].z = fmaf(v, w.z, acc[j].z);
                acc[j].w = fmaf(v, w.w, acc[j].w);
            }
        }
    }
    int gy = by*8 + ly, gx = bx*16 + lx;
    float* dst = g_fm + ((size_t)k*HWPIX + (size_t)gy*WW + gx)*64 + 32;
#pragma unroll
    for (int j = 0; j < 8; j++) ((float4*)dst)[j] = acc[j];
}

// ======================= mpn1: 64 -> 64, relu =======================
__global__ void __launch_bounds__(128, 1) mpn1_kernel(const float* __restrict__ kw,
                                                      const float* __restrict__ bw)
{
    extern __shared__ float sm[];
    float* tile = sm;             // 64*180 = 11520
    float* wgt  = sm + 11520;     // 36864
    int tid = threadIdx.x;
    for (int i = tid; i < 9216; i += 128) ((float4*)wgt)[i] = ((const float4*)kw)[i];

    int bx = blockIdx.x, by = blockIdx.y, k = blockIdx.z;
    const float* src = g_fm + (size_t)k*HWPIX*64;
    for (int idx = tid; idx < 2880; idx += 128) {
        int c4 = idx & 15, pl = idx >> 4;
        int rr = pl/18, cc = pl - rr*18;
        int gy = by*8 + rr - 1, gx = bx*16 + cc - 1;
        float4 v = make_float4(0.f,0.f,0.f,0.f);
        if (gy >= 0 && gy < HH && gx >= 0 && gx < WW)
            v = *(const float4*)&src[((size_t)gy*WW + gx)*64 + c4*4];
        tile[(c4*4+0)*180 + pl] = v.x;
        tile[(c4*4+1)*180 + pl] = v.y;
        tile[(c4*4+2)*180 + pl] = v.z;
        tile[(c4*4+3)*180 + pl] = v.w;
    }
    __syncthreads();

    int lx = tid & 15, ly = tid >> 4;
    float4 acc[16];
#pragma unroll
    for (int j = 0; j < 16; j++) acc[j] = ((const float4*)bw)[j];

    for (int dy = 0; dy < 3; dy++)
    for (int dx = 0; dx < 3; dx++) {
        const float* wr = wgt + (size_t)(dy*3 + dx)*64*64;
        int tb = (ly + dy)*18 + (lx + dx);
        for (int ic = 0; ic < 64; ic++) {
            float v = tile[ic*180 + tb];
            const float4* w4 = (const float4*)(wr + ic*64);
#pragma unroll
            for (int j = 0; j < 16; j++) {
                float4 w = w4[j];
                acc[j].x = fmaf(v, w.x, acc[j].x);
                acc[j].y = fmaf(v, w.y, acc[j].y);
                acc[j].z = fmaf(v, w.z, acc[j].z);
                acc[j].w = fmaf(v, w.w, acc[j].w);
            }
        }
    }
    int gy = by*8 + ly, gx = bx*16 + lx;
    float* dst = g_t64 + ((size_t)k*HWPIX + (size_t)gy*WW + gx)*64;
#pragma unroll
    for (int j = 0; j < 16; j++) {
        float4 o;
        o.x = fmaxf(acc[j].x, 0.f); o.y = fmaxf(acc[j].y, 0.f);
        o.z = fmaxf(acc[j].z, 0.f); o.w = fmaxf(acc[j].w, 0.f);
        ((float4*)dst)[j] = o;
    }
}

// ============ mpn2 + sigmoid + cumprod compositing (fused) ============
__global__ void __launch_bounds__(128, 1) mpn2_kernel(const float* __restrict__ kw,
                                                      const float* __restrict__ bw)
{
    extern __shared__ float sm[];
    float* tile = sm;
    float* wgt  = sm + 11520;
    int tid = threadIdx.x;
    for (int i = tid; i < 9216; i += 128) ((float4*)wgt)[i] = ((const float4*)kw)[i];

    int bx = blockIdx.x, by = blockIdx.y, k = blockIdx.z;
    const float* src = g_t64 + (size_t)k*HWPIX*64;
    for (int idx = tid; idx < 2880; idx += 128) {
        int c4 = idx & 15, pl = idx >> 4;
        int rr = pl/18, cc = pl - rr*18;
        int gy = by*8 + rr - 1, gx = bx*16 + cc - 1;
        float4 v = make_float4(0.f,0.f,0.f,0.f);
        if (gy >= 0 && gy < HH && gx >= 0 && gx < WW)
            v = *(const float4*)&src[((size_t)gy*WW + gx)*64 + c4*4];
        tile[(c4*4+0)*180 + pl] = v.x;
        tile[(c4*4+1)*180 + pl] = v.y;
        tile[(c4*4+2)*180 + pl] = v.z;
        tile[(c4*4+3)*180 + pl] = v.w;
    }
    __syncthreads();

    int lx = tid & 15, ly = tid >> 4;
    float4 acc[16];
#pragma unroll
    for (int j = 0; j < 16; j++) acc[j] = ((const float4*)bw)[j];

    for (int dy = 0; dy < 3; dy++)
    for (int dx = 0; dx < 3; dx++) {
        const float* wr = wgt + (size_t)(dy*3 + dx)*64*64;
        int tb = (ly + dy)*18 + (lx + dx);
        for (int ic = 0; ic < 64; ic++) {
            float v = tile[ic*180 + tb];
            const float4* w4 = (const float4*)(wr + ic*64);
#pragma unroll
            for (int j = 0; j < 16; j++) {
                float4 w = w4[j];
                acc[j].x = fmaf(v, w.x, acc[j].x);
                acc[j].y = fmaf(v, w.y, acc[j].y);
                acc[j].z = fmaf(v, w.z, acc[j].z);
                acc[j].w = fmaf(v, w.w, acc[j].w);
            }
        }
    }
    // m = sigmoid(acc); alpha_c = prod_{j<c}(1-m_j); fuse = sum fm*m*alpha
    int gy = by*8 + ly, gx = bx*16 + lx;
    const float* fmc = g_fm + ((size_t)k*HWPIX + (size_t)gy*WW + gx)*64;
    float alpha = 1.f, fuse = 0.f;
#pragma unroll
    for (int j = 0; j < 16; j++) {
        float4 f = ((const float4*)fmc)[j];
        float m;
        m = 1.f/(1.f + expf(-acc[j].x)); fuse += f.x*m*alpha; alpha *= (1.f - m);
        m = 1.f/(1.f + expf(-acc[j].y)); fuse += f.y*m*alpha; alpha *= (1.f - m);
        m = 1.f/(1.f + expf(-acc[j].z)); fuse += f.z*m*alpha; alpha *= (1.f - m);
        m = 1.f/(1.f + expf(-acc[j].w)); fuse += f.w*m*alpha; alpha *= (1.f - m);
    }
    g_fuse[((size_t)gy*WW + gx)*8 + k] = fuse;
}

// ======================= un1: 8 -> 32, relu =======================
__global__ void un1_kernel(const float* __restrict__ kw, const float* __restrict__ bw)
{
    __shared__ float wgt[2304]; // 3*3*8*32
    int tx = threadIdx.x, ty = threadIdx.y;
    int tid = ty*32 + tx;
    for (int i = tid; i < 2304; i += 256) wgt[i] = kw[i];
    __syncthreads();

    int x = blockIdx.x*32 + tx, y = blockIdx.y*8 + ty;
    float4 acc[8];
#pragma unroll
    for (int j = 0; j < 8; j++) acc[j] = ((const float4*)bw)[j];

    for (int dy = 0; dy < 3; dy++)
    for (int dx = 0; dx < 3; dx++) {
        int iy = y + dy - 1, ix = x + dx - 1;
        if (iy < 0 || iy >= HH || ix < 0 || ix >= WW) continue;
        const float* fp = g_fuse + ((size_t)iy*WW + ix)*8;
        float4 f0 = ((const float4*)fp)[0];
        float4 f1 = ((const float4*)fp)[1];
        float fv[8] = {f0.x,f0.y,f0.z,f0.w,f1.x,f1.y,f1.z,f1.w};
        const float* wr = wgt + (dy*3 + dx)*256;
#pragma unroll
        for (int ic = 0; ic < 8; ic++) {
            float v = fv[ic];
            const float4* w4 = (const float4*)(wr + ic*32);
#pragma unroll
            for (int j = 0; j < 8; j++) {
                float4 w = w4[j];
                acc[j].x = fmaf(v, w.x, acc[j].x);
                acc[j].y = fmaf(v, w.y, acc[j].y);
                acc[j].z = fmaf(v, w.z, acc[j].z);
                acc[j].w = fmaf(v, w.w, acc[j].w);
            }
        }
    }
    float* dst = g_u32 + ((size_t)y*WW + x)*32;
#pragma unroll
    for (int j = 0; j < 8; j++) {
        float4 o;
        o.x = fmaxf(acc[j].x, 0.f); o.y = fmaxf(acc[j].y, 0.f);
        o.z = fmaxf(acc[j].z, 0.f); o.w = fmaxf(acc[j].w, 0.f);
        ((float4*)dst)[j] = o;
    }
}

// ======================= un2: 32 -> 3 =======================
__global__ void un2_kernel(const float* __restrict__ kw, const float* __restrict__ bw,
                           float* __restrict__ out)
{
    __shared__ float wgt[864]; // 3*3*32*3
    int tx = threadIdx.x, ty = threadIdx.y;
    int tid = ty*32 + tx;
    for (int i = tid; i < 864; i += 256) wgt[i] = kw[i];
    __syncthreads();

    int x = blockIdx.x*32 + tx, y = blockIdx.y*8 + ty;
    float a0 = bw[0], a1 = bw[1], a2 = bw[2];

    for (int dy = 0; dy < 3; dy++)
    for (int dx = 0; dx < 3; dx++) {
        int iy = y + dy - 1, ix = x + dx - 1;
        if (iy < 0 || iy >= HH || ix < 0 || ix >= WW) continue;
        const float* up = g_u32 + ((size_t)iy*WW + ix)*32;
        const float* wr = wgt + (dy*3 + dx)*96;
#pragma unroll
        for (int ic4 = 0; ic4 < 8; ic4++) {
            float4 v = ((const float4*)up)[ic4];
            float vv[4] = {v.x, v.y, v.z, v.w};
#pragma unroll
            for (int j = 0; j < 4; j++) {
                int ic = ic4*4 + j;
                a0 = fmaf(vv[j], wr[ic*3 + 0], a0);
                a1 = fmaf(vv[j], wr[ic*3 + 1], a1);
                a2 = fmaf(vv[j], wr[ic*3 + 2], a2);
            }
        }
    }
    float* dst = out + ((size_t)y*WW + x)*3;
    dst[0] = a0; dst[1] = a1; dst[2] = a2;
}

// ======================= launch =======================
extern "C" void kernel_launch(void* const* d_in, const int* in_sizes, int n_in,
                              void* d_out, int out_size)
{
    const float* colors = (const float*)d_in[0];
    const float* ray    = (const float*)d_in[1];
    const float* zbufs  = (const float*)d_in[2];
    const float* W1 = (const float*)d_in[3];
    const float* b1 = (const float*)d_in[4];
    const float* W2 = (const float*)d_in[5];
    const float* b2 = (const float*)d_in[6];
    const float* W3 = (const float*)d_in[7];
    const float* b3 = (const float*)d_in[8];
    const float* W4 = (const float*)d_in[9];
    const float* b4 = (const float*)d_in[10];
    const float* k_sup1 = (const float*)d_in[11];
    const float* b_sup1 = (const float*)d_in[12];
    const float* k_sup2 = (const float*)d_in[13];
    const float* b_sup2 = (const float*)d_in[14];
    const float* k_mpn1 = (const float*)d_in[15];
    const float* b_mpn1 = (const float*)d_in[16];
    const float* k_mpn2 = (const float*)d_in[17];
    const float* b_mpn2 = (const float*)d_in[18];
    const float* k_un1  = (const float*)d_in[19];
    const float* b_un1  = (const float*)d_in[20];
    const float* k_un2  = (const float*)d_in[21];
    const float* b_un2  = (const float*)d_in[22];
    float* out = (float*)d_out;

    cudaFuncSetAttribute(mlp_kernel,  cudaFuncAttributeMaxDynamicSharedMemorySize, MLP_SMEM_BYTES);
    cudaFuncSetAttribute(sup2_kernel, cudaFuncAttributeMaxDynamicSharedMemorySize, 59904);
    cudaFuncSetAttribute(mpn1_kernel, cudaFuncAttributeMaxDynamicSharedMemorySize, 193536);
    cudaFuncSetAttribute(mpn2_kernel, cudaFuncAttributeMaxDynamicSharedMemorySize, 193536);

    mlp_kernel<<<32768, 128, MLP_SMEM_BYTES>>>(ray, zbufs, W1,b1, W2,b2, W3,b3, W4,b4);
    sup1_kernel<<<dim3(16,64,8), dim3(32,8)>>>(colors, k_sup1, b_sup1);
    sup2_kernel<<<dim3(32,64,8), 128, 59904>>>(k_sup2, b_sup2);
    mpn1_kernel<<<dim3(32,64,8), 128, 193536>>>(k_mpn1, b_mpn1);
    mpn2_kernel<<<dim3(32,64,8), 128, 193536>>>(k_mpn2, b_mpn2);
    un1_kernel<<<dim3(16,64), dim3(32,8)>>>(k_un1, b_un1);
    un2_kernel<<<dim3(16,64), dim3(32,8)>>>(k_un2, b_un2, out);
}